// round 3
// baseline (speedup 1.0000x reference)
#include <cuda_runtime.h>

#define B 64
#define T 2048
#define D 768
#define P 1024
#define TOPK 8
#define NCH 16
#define CHUNK 128     // T / NCH
#define D4 192        // D / 4
#define OC 8          // output columns per block in matmul kernels
#define WPAD 772      // 768 + 4 float pad: conflict-free smem rows

// ---------------- scratch (device globals; no allocations allowed) ----------
__device__ float g_part[B * NCH * D];   // token-max partials (3 MB)
__device__ float g_xmean[B * D];        // max over tokens
__device__ float g_pnorm[P * D];        // l2-normalized prompts
__device__ float g_xnorm[B * D];        // x_proj, then normalized in place
__device__ float g_sim[B * P];          // similarity matrix
__device__ int   g_counts[P];           // vote bincount
__device__ int   g_mid[TOPK];           // winning prompt ids

__device__ __forceinline__ float4 f4max(float4 a, float4 b) {
    return make_float4(fmaxf(a.x, b.x), fmaxf(a.y, b.y),
                       fmaxf(a.z, b.z), fmaxf(a.w, b.w));
}

// ---------------- K1: partial max over token chunks (HBM-bound) -------------
__global__ __launch_bounds__(192) void k1_maxpart(const float* __restrict__ x) {
    int blk = blockIdx.x;            // b * NCH + ch  (1024 blocks)
    int b   = blk >> 4;
    int ch  = blk & (NCH - 1);
    int tid = threadIdx.x;           // 0..191

    if (blk == 0) {                  // re-zero vote counts every graph replay
        for (int i = tid; i < P; i += 192) g_counts[i] = 0;
    }

    const float4* xp = reinterpret_cast<const float4*>(x)
                     + (size_t)(b * T + ch * CHUNK) * D4 + tid;
    float4 a0 = xp[0 * D4];
    float4 a1 = xp[1 * D4];
    float4 a2 = xp[2 * D4];
    float4 a3 = xp[3 * D4];
#pragma unroll 4
    for (int t = 4; t < CHUNK; t += 4) {
        a0 = f4max(a0, xp[(t + 0) * D4]);
        a1 = f4max(a1, xp[(t + 1) * D4]);
        a2 = f4max(a2, xp[(t + 2) * D4]);
        a3 = f4max(a3, xp[(t + 3) * D4]);
    }
    float4 m = f4max(f4max(a0, a1), f4max(a2, a3));
    reinterpret_cast<float4*>(g_part)[(size_t)blk * D4 + tid] = m;
}

// ---------------- K2: finalize max over chunks -------------------------------
__global__ __launch_bounds__(192) void k2_maxfin() {
    int b   = blockIdx.x;
    int tid = threadIdx.x;           // 0..191
    const float4* pp = reinterpret_cast<const float4*>(g_part)
                     + (size_t)b * NCH * D4 + tid;
    float4 m = pp[0];
#pragma unroll
    for (int ch = 1; ch < NCH; ch++) m = f4max(m, pp[ch * D4]);
    reinterpret_cast<float4*>(g_xmean)[b * D4 + tid] = m;
}

// ---------------- row l2-normalize (192 threads, one row per block) ----------
__device__ __forceinline__ void rownorm_body(const float* __restrict__ in,
                                             float* __restrict__ out) {
    int r   = blockIdx.x;
    int tid = threadIdx.x;           // 0..191
    float4 v = reinterpret_cast<const float4*>(in)[r * D4 + tid];
    float s = v.x * v.x + v.y * v.y + v.z * v.z + v.w * v.w;
#pragma unroll
    for (int o = 16; o; o >>= 1) s += __shfl_xor_sync(0xffffffffu, s, o);
    __shared__ float ws[6];
    if ((tid & 31) == 0) ws[tid >> 5] = s;
    __syncthreads();
    float tot = ws[0] + ws[1] + ws[2] + ws[3] + ws[4] + ws[5];
    float sc  = rsqrtf(fmaxf(tot, 1e-12f));
    v.x *= sc; v.y *= sc; v.z *= sc; v.w *= sc;
    reinterpret_cast<float4*>(out)[r * D4 + tid] = v;
}

__global__ __launch_bounds__(192) void k_pnorm(const float* __restrict__ prompt) {
    rownorm_body(prompt, g_pnorm);
}
__global__ __launch_bounds__(192) void k_xnorm() {
    rownorm_body(g_xnorm, g_xnorm);   // each thread touches only its own float4
}

// ---------------- K3: x_proj[b,o] = sum_i x_mean[b,i] * W[o,i] ---------------
__global__ __launch_bounds__(256) void k3_proj(const float* __restrict__ W) {
    __shared__ float Ws[OC * WPAD];
    int o0  = blockIdx.x * OC;       // 96 blocks
    int tid = threadIdx.x;           // 0..255
    for (int idx = tid; idx < OC * D4; idx += 256) {
        int o = idx / D4, i4 = idx % D4;
        float4 w = reinterpret_cast<const float4*>(W)[(o0 + o) * D4 + i4];
        *reinterpret_cast<float4*>(&Ws[o * WPAD + i4 * 4]) = w;
    }
    __syncthreads();
    int ol = tid & (OC - 1);
    int b0 = tid >> 3;               // 0..31
#pragma unroll
    for (int rep = 0; rep < 2; rep++) {
        int b = b0 + rep * 32;
        const float4* xm = reinterpret_cast<const float4*>(g_xmean) + b * D4;
        const float4* wv = reinterpret_cast<const float4*>(&Ws[ol * WPAD]);
        float4 acc = make_float4(0.f, 0.f, 0.f, 0.f);
#pragma unroll 4
        for (int i4 = 0; i4 < D4; i4++) {
            float4 w = wv[i4], xv = xm[i4];
            acc.x += w.x * xv.x; acc.y += w.y * xv.y;
            acc.z += w.z * xv.z; acc.w += w.w * xv.w;
        }
        g_xnorm[b * D + o0 + ol] = acc.x + acc.y + acc.z + acc.w;
    }
}

// ---------------- K4: similarity[b,p] = x_norm[b] . prompt_norm[p] ----------
__global__ __launch_bounds__(256) void k4_sim() {
    __shared__ float Ps[OC * WPAD];
    int p0  = blockIdx.x * OC;       // 128 blocks
    int tid = threadIdx.x;           // 0..255
    for (int idx = tid; idx < OC * D4; idx += 256) {
        int p = idx / D4, i4 = idx % D4;
        float4 w = reinterpret_cast<const float4*>(g_pnorm)[(p0 + p) * D4 + i4];
        *reinterpret_cast<float4*>(&Ps[p * WPAD + i4 * 4]) = w;
    }
    __syncthreads();
    int pl = tid & (OC - 1);
    int b0 = tid >> 3;
#pragma unroll
    for (int rep = 0; rep < 2; rep++) {
        int b = b0 + rep * 32;
        const float4* xm = reinterpret_cast<const float4*>(g_xnorm) + b * D4;
        const float4* pv = reinterpret_cast<const float4*>(&Ps[pl * WPAD]);
        float4 acc = make_float4(0.f, 0.f, 0.f, 0.f);
#pragma unroll 4
        for (int i4 = 0; i4 < D4; i4++) {
            float4 w = pv[i4], xv = xm[i4];
            acc.x += w.x * xv.x; acc.y += w.y * xv.y;
            acc.z += w.z * xv.z; acc.w += w.w * xv.w;
        }
        g_sim[b * P + p0 + pl] = acc.x + acc.y + acc.z + acc.w;
    }
}

// ---------------- K5: per-row top-8 (ties -> lower index) + bincount --------
__global__ __launch_bounds__(256) void k5_top8() {
    __shared__ float sv[P];
    __shared__ float bv[256];
    __shared__ int   bi[256];
    int b   = blockIdx.x;
    int tid = threadIdx.x;           // 0..255
    for (int i = tid; i < P; i += 256) sv[i] = g_sim[b * P + i];
    __syncthreads();
    for (int r = 0; r < TOPK; r++) {
        float best = -3.4e38f; int idx = 0;
        for (int j = tid; j < P; j += 256) {   // ascending j: strict '>' keeps lowest idx
            float v = sv[j];
            if (v > best) { best = v; idx = j; }
        }
        bv[tid] = best; bi[tid] = idx;
        __syncthreads();
        for (int s = 128; s > 0; s >>= 1) {
            if (tid < s) {
                float v2 = bv[tid + s]; int i2 = bi[tid + s];
                if (v2 > bv[tid] || (v2 == bv[tid] && i2 < bi[tid])) {
                    bv[tid] = v2; bi[tid] = i2;
                }
            }
            __syncthreads();
        }
        if (tid == 0) {
            atomicAdd(&g_counts[bi[0]], 1);
            sv[bi[0]] = -3.4e38f;
        }
        __syncthreads();
    }
}

// ---------------- K6: vote top-8 of counts + reduce_sim ----------------------
__global__ __launch_bounds__(256) void k6_vote(float* __restrict__ out) {
    __shared__ int   cv[P];
    __shared__ int   bvv[256];
    __shared__ int   bii[256];
    __shared__ int   ms[TOPK];
    __shared__ float wsum[8];
    int tid = threadIdx.x;           // 0..255
    for (int i = tid; i < P; i += 256) cv[i] = g_counts[i];
    __syncthreads();
    for (int r = 0; r < TOPK; r++) {
        int best = -1, idx = 0;
        for (int j = tid; j < P; j += 256) {
            int v = cv[j];
            if (v > best) { best = v; idx = j; }
        }
        bvv[tid] = best; bii[tid] = idx;
        __syncthreads();
        for (int s = 128; s > 0; s >>= 1) {
            if (tid < s) {
                if (bvv[tid + s] > bvv[tid] ||
                    (bvv[tid + s] == bvv[tid] && bii[tid + s] < bii[tid])) {
                    bvv[tid] = bvv[tid + s]; bii[tid] = bii[tid + s];
                }
            }
            __syncthreads();
        }
        if (tid == 0) { ms[r] = bii[0]; g_mid[r] = bii[0]; cv[bii[0]] = -1; }
        __syncthreads();
    }
    // reduce_sim = sum_{b,j} sim[b, mid[j]] / B
    float s = 0.f;
    for (int t = tid; t < B * TOPK; t += 256) {
        int b = t >> 3, j = t & 7;
        s += g_sim[b * P + ms[j]];
    }
#pragma unroll
    for (int o = 16; o; o >>= 1) s += __shfl_xor_sync(0xffffffffu, s, o);
    if ((tid & 31) == 0) wsum[tid >> 5] = s;
    __syncthreads();
    if (tid == 0) {
        float tot = 0.f;
#pragma unroll
        for (int w = 0; w < 8; w++) tot += wsum[w];
        out[0] = tot / (float)B;
    }
}

// ---------------- K7: gather batched_prompt ----------------------------------
__global__ __launch_bounds__(192) void k7_gather(const float* __restrict__ prompt,
                                                 float* __restrict__ out) {
    int blk = blockIdx.x;            // b*8 + j, 512 blocks
    int j   = blk & 7;
    int pid = g_mid[j];
    int tid = threadIdx.x;           // 0..191
    const float* src = prompt + (size_t)pid * D;
    float* dst = out + 1 + (size_t)blk * D;   // out[0] = reduce_sim
#pragma unroll
    for (int k = 0; k < 4; k++) dst[tid + k * 192] = src[tid + k * 192];
}

// ---------------- launch ------------------------------------------------------
extern "C" void kernel_launch(void* const* d_in, const int* in_sizes, int n_in,
                              void* d_out, int out_size) {
    const float* x      = (const float*)d_in[0];
    const float* prompt = (const float*)d_in[1];
    const float* W      = (const float*)d_in[2];
    float* out          = (float*)d_out;

    k1_maxpart<<<B * NCH, 192>>>(x);
    k2_maxfin<<<B, 192>>>();
    k_pnorm<<<P, 192>>>(prompt);
    k3_proj<<<D / OC, 256>>>(W);
    k_xnorm<<<B, 192>>>();
    k4_sim<<<P / OC, 256>>>();
    k5_top8<<<B, 256>>>();
    k6_vote<<<1, 256>>>(out);
    k7_gather<<<B * TOPK, 192>>>(prompt, out);
}

// round 5
// speedup vs baseline: 1.2378x; 1.2378x over previous
#include <cuda_runtime.h>

#define B 64
#define T 2048
#define D 768
#define P 1024
#define TOPK 8
#define NCH 16
#define CHUNK 128     // T / NCH
#define D4 192        // D / 4 (float4 per row)
#define OC 8          // output columns per block in matmul kernels
#define KS 4          // split-K factor
#define KC4 48        // float4 per split (192 floats)
#define XSTR 196      // padded smem row stride (floats): 196 % 32 == 4 -> conflict-free

// ---------------- scratch (device globals; no allocations allowed) ----------
__device__ float g_part[B * NCH * D];   // token-max partials (3 MB)
__device__ float g_xmean[B * D];        // max over tokens
__device__ float g_pnorm[P * D];        // l2-normalized prompts
__device__ float g_xnorm[B * D];        // normalized x_proj
__device__ float g_p3[KS][B][D];        // split-K partials for proj
__device__ float g_p4[KS][B][P];        // split-K partials for sim
__device__ float g_sim[B * P];          // similarity matrix
__device__ int   g_counts[P];           // vote bincount
__device__ int   g_mid[TOPK];           // winning prompt ids

__device__ __forceinline__ float4 f4max(float4 a, float4 b) {
    return make_float4(fmaxf(a.x, b.x), fmaxf(a.y, b.y),
                       fmaxf(a.z, b.z), fmaxf(a.w, b.w));
}
__device__ __forceinline__ float4 f4add(float4 a, float4 b) {
    return make_float4(a.x + b.x, a.y + b.y, a.z + b.z, a.w + b.w);
}

// ---------------- K1: partial max over token chunks (HBM-bound) -------------
__global__ __launch_bounds__(192) void k1_maxpart(const float* __restrict__ x) {
    int blk = blockIdx.x;            // b * NCH + ch  (1024 blocks)
    int b   = blk >> 4;
    int ch  = blk & (NCH - 1);
    int tid = threadIdx.x;           // 0..191

    if (blk == 0) {                  // re-zero vote counts every graph replay
        for (int i = tid; i < P; i += 192) g_counts[i] = 0;
    }

    const float4* xp = reinterpret_cast<const float4*>(x)
                     + (size_t)(b * T + ch * CHUNK) * D4 + tid;
    float4 a0 = xp[0 * D4];
    float4 a1 = xp[1 * D4];
    float4 a2 = xp[2 * D4];
    float4 a3 = xp[3 * D4];
#pragma unroll 4
    for (int t = 4; t < CHUNK; t += 4) {
        a0 = f4max(a0, xp[(t + 0) * D4]);
        a1 = f4max(a1, xp[(t + 1) * D4]);
        a2 = f4max(a2, xp[(t + 2) * D4]);
        a3 = f4max(a3, xp[(t + 3) * D4]);
    }
    float4 m = f4max(f4max(a0, a1), f4max(a2, a3));
    reinterpret_cast<float4*>(g_part)[(size_t)blk * D4 + tid] = m;
}

// ---------------- K2: finalize max over chunks -------------------------------
__global__ __launch_bounds__(192) void k2_maxfin() {
    int b   = blockIdx.x;
    int tid = threadIdx.x;           // 0..191
    const float4* pp = reinterpret_cast<const float4*>(g_part)
                     + (size_t)b * NCH * D4 + tid;
    float4 m = pp[0];
#pragma unroll
    for (int ch = 1; ch < NCH; ch++) m = f4max(m, pp[ch * D4]);
    reinterpret_cast<float4*>(g_xmean)[b * D4 + tid] = m;
}

// ---------------- k_pnorm: l2-normalize prompts ------------------------------
__global__ __launch_bounds__(192) void k_pnorm(const float* __restrict__ prompt) {
    int r   = blockIdx.x;
    int tid = threadIdx.x;           // 0..191
    float4 v = reinterpret_cast<const float4*>(prompt)[r * D4 + tid];
    float s = v.x * v.x + v.y * v.y + v.z * v.z + v.w * v.w;
#pragma unroll
    for (int o = 16; o; o >>= 1) s += __shfl_xor_sync(0xffffffffu, s, o);
    __shared__ float ws[6];
    if ((tid & 31) == 0) ws[tid >> 5] = s;
    __syncthreads();
    float tot = ws[0] + ws[1] + ws[2] + ws[3] + ws[4] + ws[5];
    float sc  = rsqrtf(fmaxf(tot, 1e-12f));
    v.x *= sc; v.y *= sc; v.z *= sc; v.w *= sc;
    reinterpret_cast<float4*>(g_pnorm)[r * D4 + tid] = v;
}

// ---------------- K3p: split-K partial proj, x & W staged in SMEM -----------
// grid = (D/OC) * KS = 96*4 = 384 blocks of 256
__global__ __launch_bounds__(256) void k3p(const float* __restrict__ W) {
    __shared__ float xs[B * XSTR];     // 64 x 196 floats
    __shared__ float ws[OC * XSTR];    // 8 x 196 floats
    int ot = blockIdx.x >> 2;          // 0..95
    int ks = blockIdx.x & 3;           // 0..3
    int o0 = ot * OC;
    int k4 = ks * KC4;                 // float4 offset into K
    int tid = threadIdx.x;

    for (int idx = tid; idx < B * KC4; idx += 256) {
        int b = idx / KC4, i = idx % KC4;
        float4 v = reinterpret_cast<const float4*>(g_xmean)[b * D4 + k4 + i];
        *reinterpret_cast<float4*>(&xs[b * XSTR + i * 4]) = v;
    }
    for (int idx = tid; idx < OC * KC4; idx += 256) {
        int o = idx / KC4, i = idx % KC4;
        float4 v = reinterpret_cast<const float4*>(W)[(o0 + o) * D4 + k4 + i];
        *reinterpret_cast<float4*>(&ws[o * XSTR + i * 4]) = v;
    }
    __syncthreads();

    int ol = tid & (OC - 1);
    int b0 = tid >> 3;
#pragma unroll
    for (int rep = 0; rep < 2; rep++) {
        int b = b0 + rep * 32;
        const float* xr = &xs[b * XSTR];
        const float* wr = &ws[ol * XSTR];
        float4 acc = make_float4(0.f, 0.f, 0.f, 0.f);
#pragma unroll
        for (int i = 0; i < KC4; i++) {
            float4 a = *reinterpret_cast<const float4*>(xr + i * 4);
            float4 w = *reinterpret_cast<const float4*>(wr + i * 4);
            acc.x += a.x * w.x; acc.y += a.y * w.y;
            acc.z += a.z * w.z; acc.w += a.w * w.w;
        }
        g_p3[ks][b][o0 + ol] = acc.x + acc.y + acc.z + acc.w;
    }
}

// ---------------- K3c: combine split-K partials + l2-normalize ---------------
__global__ __launch_bounds__(192) void k3c_xnorm() {
    int b   = blockIdx.x;
    int tid = threadIdx.x;           // 0..191
    float4 v = f4add(
        f4add(reinterpret_cast<const float4*>(g_p3[0][b])[tid],
              reinterpret_cast<const float4*>(g_p3[1][b])[tid]),
        f4add(reinterpret_cast<const float4*>(g_p3[2][b])[tid],
              reinterpret_cast<const float4*>(g_p3[3][b])[tid]));
    float s = v.x * v.x + v.y * v.y + v.z * v.z + v.w * v.w;
#pragma unroll
    for (int o = 16; o; o >>= 1) s += __shfl_xor_sync(0xffffffffu, s, o);
    __shared__ float wsm[6];
    if ((tid & 31) == 0) wsm[tid >> 5] = s;
    __syncthreads();
    float tot = wsm[0] + wsm[1] + wsm[2] + wsm[3] + wsm[4] + wsm[5];
    float sc  = rsqrtf(fmaxf(tot, 1e-12f));
    v.x *= sc; v.y *= sc; v.z *= sc; v.w *= sc;
    reinterpret_cast<float4*>(g_xnorm)[b * D4 + tid] = v;
}

// ---------------- K4p: split-K partial similarity ---------------------------
// grid = (P/OC) * KS = 128*4 = 512 blocks of 256
__global__ __launch_bounds__(256) void k4p() {
    __shared__ float xs[B * XSTR];
    __shared__ float ps[OC * XSTR];
    int pt = blockIdx.x >> 2;          // 0..127
    int ks = blockIdx.x & 3;
    int p0 = pt * OC;
    int k4 = ks * KC4;
    int tid = threadIdx.x;

    for (int idx = tid; idx < B * KC4; idx += 256) {
        int b = idx / KC4, i = idx % KC4;
        float4 v = reinterpret_cast<const float4*>(g_xnorm)[b * D4 + k4 + i];
        *reinterpret_cast<float4*>(&xs[b * XSTR + i * 4]) = v;
    }
    for (int idx = tid; idx < OC * KC4; idx += 256) {
        int p = idx / KC4, i = idx % KC4;
        float4 v = reinterpret_cast<const float4*>(g_pnorm)[(p0 + p) * D4 + k4 + i];
        *reinterpret_cast<float4*>(&ps[p * XSTR + i * 4]) = v;
    }
    __syncthreads();

    int pl = tid & (OC - 1);
    int b0 = tid >> 3;
#pragma unroll
    for (int rep = 0; rep < 2; rep++) {
        int b = b0 + rep * 32;
        const float* xr = &xs[b * XSTR];
        const float* pr = &ps[pl * XSTR];
        float4 acc = make_float4(0.f, 0.f, 0.f, 0.f);
#pragma unroll
        for (int i = 0; i < KC4; i++) {
            float4 a = *reinterpret_cast<const float4*>(xr + i * 4);
            float4 w = *reinterpret_cast<const float4*>(pr + i * 4);
            acc.x += a.x * w.x; acc.y += a.y * w.y;
            acc.z += a.z * w.z; acc.w += a.w * w.w;
        }
        g_p4[ks][b][p0 + pl] = acc.x + acc.y + acc.z + acc.w;
    }
}

// ---------------- K4c: combine sim partials ----------------------------------
// B*P/4 = 16384 float4; 64 blocks x 256 threads
__global__ __launch_bounds__(256) void k4c() {
    int idx = blockIdx.x * 256 + threadIdx.x;   // float4 index into [B][P]
    const float4* p0 = reinterpret_cast<const float4*>(&g_p4[0][0][0]);
    const float4* p1 = reinterpret_cast<const float4*>(&g_p4[1][0][0]);
    const float4* p2 = reinterpret_cast<const float4*>(&g_p4[2][0][0]);
    const float4* p3 = reinterpret_cast<const float4*>(&g_p4[3][0][0]);
    float4 v = f4add(f4add(p0[idx], p1[idx]), f4add(p2[idx], p3[idx]));
    reinterpret_cast<float4*>(g_sim)[idx] = v;
}

// ---------------- K5: per-row top-8 (ties -> lower index) + bincount --------
__global__ __launch_bounds__(256) void k5_top8() {
    __shared__ float sv[P];
    __shared__ float bv[256];
    __shared__ int   bi[256];
    int b   = blockIdx.x;
    int tid = threadIdx.x;           // 0..255
    for (int i = tid; i < P; i += 256) sv[i] = g_sim[b * P + i];
    __syncthreads();
    for (int r = 0; r < TOPK; r++) {
        float best = -3.4e38f; int idx = 0;
        for (int j = tid; j < P; j += 256) {   // ascending j: strict '>' keeps lowest idx
            float v = sv[j];
            if (v > best) { best = v; idx = j; }
        }
        bv[tid] = best; bi[tid] = idx;
        __syncthreads();
        for (int s = 128; s > 0; s >>= 1) {
            if (tid < s) {
                float v2 = bv[tid + s]; int i2 = bi[tid + s];
                if (v2 > bv[tid] || (v2 == bv[tid] && i2 < bi[tid])) {
                    bv[tid] = v2; bi[tid] = i2;
                }
            }
            __syncthreads();
        }
        if (tid == 0) {
            atomicAdd(&g_counts[bi[0]], 1);
            sv[bi[0]] = -3.4e38f;
        }
        __syncthreads();
    }
}

// ---------------- K6: vote top-8 of counts + reduce_sim ----------------------
__global__ __launch_bounds__(256) void k6_vote(float* __restrict__ out) {
    __shared__ int   cv[P];
    __shared__ int   bvv[256];
    __shared__ int   bii[256];
    __shared__ int   ms[TOPK];
    __shared__ float wsum[8];
    int tid = threadIdx.x;           // 0..255
    for (int i = tid; i < P; i += 256) cv[i] = g_counts[i];
    __syncthreads();
    for (int r = 0; r < TOPK; r++) {
        int best = -1, idx = 0;
        for (int j = tid; j < P; j += 256) {
            int v = cv[j];
            if (v > best) { best = v; idx = j; }
        }
        bvv[tid] = best; bii[tid] = idx;
        __syncthreads();
        for (int s = 128; s > 0; s >>= 1) {
            if (tid < s) {
                if (bvv[tid + s] > bvv[tid] ||
                    (bvv[tid + s] == bvv[tid] && bii[tid + s] < bii[tid])) {
                    bvv[tid] = bvv[tid + s]; bii[tid] = bii[tid + s];
                }
            }
            __syncthreads();
        }
        if (tid == 0) { ms[r] = bii[0]; g_mid[r] = bii[0]; cv[bii[0]] = -1; }
        __syncthreads();
    }
    // reduce_sim = sum_{b,j} sim[b, mid[j]] / B
    float s = 0.f;
    for (int t = tid; t < B * TOPK; t += 256) {
        int b = t >> 3, j = t & 7;
        s += g_sim[b * P + ms[j]];
    }
#pragma unroll
    for (int o = 16; o; o >>= 1) s += __shfl_xor_sync(0xffffffffu, s, o);
    if ((tid & 31) == 0) wsum[tid >> 5] = s;
    __syncthreads();
    if (tid == 0) {
        float tot = 0.f;
#pragma unroll
        for (int w = 0; w < 8; w++) tot += wsum[w];
        out[0] = tot / (float)B;
    }
}

// ---------------- K7: gather batched_prompt ----------------------------------
__global__ __launch_bounds__(192) void k7_gather(const float* __restrict__ prompt,
                                                 float* __restrict__ out) {
    int blk = blockIdx.x;            // b*8 + j, 512 blocks
    int j   = blk & 7;
    int pid = g_mid[j];
    int tid = threadIdx.x;           // 0..191
    const float* src = prompt + (size_t)pid * D;
    float* dst = out + 1 + (size_t)blk * D;   // out[0] = reduce_sim
#pragma unroll
    for (int k = 0; k < 4; k++) dst[tid + k * 192] = src[tid + k * 192];
}

// ---------------- launch ------------------------------------------------------
extern "C" void kernel_launch(void* const* d_in, const int* in_sizes, int n_in,
                              void* d_out, int out_size) {
    const float* x      = (const float*)d_in[0];
    const float* prompt = (const float*)d_in[1];
    const float* W      = (const float*)d_in[2];
    float* out          = (float*)d_out;

    k1_maxpart<<<B * NCH, 192>>>(x);
    k2_maxfin<<<B, 192>>>();
    k_pnorm<<<P, 192>>>(prompt);
    k3p<<<(D / OC) * KS, 256>>>(W);
    k3c_xnorm<<<B, 192>>>();
    k4p<<<(P / OC) * KS, 256>>>();
    k4c<<<B * P / 4 / 256, 256>>>();
    k5_top8<<<B, 256>>>();
    k6_vote<<<1, 256>>>(out);
    k7_gather<<<B * TOPK, 192>>>(prompt, out);
}

// round 8
// speedup vs baseline: 1.2756x; 1.0306x over previous
#include <cuda_runtime.h>

#define B 64
#define T 2048
#define D 768
#define P 1024
#define TOPK 8
#define NCH 16
#define CHUNK 128     // T / NCH
#define D4 192        // D / 4 (float4 per row)
#define OC 8          // output columns per block in matmul kernels
#define KS 8          // split-K factor
#define KC4 24        // float4 per split (96 floats)
#define XSTR 100      // padded smem row stride (floats): 100 % 32 == 4 -> conflict-free

// ---------------- scratch (device globals; no allocations allowed) ----------
__device__ float g_part[B * NCH * D];   // token-max partials (3 MB)
__device__ float g_xmean[B * D];        // max over tokens
__device__ float g_pnorm[P * D];        // l2-normalized prompts
__device__ float g_xnorm[B * D];        // normalized x_proj
__device__ float g_p3[KS][B][D];        // split-K partials for proj
__device__ float g_p4[KS][B][P];        // split-K partials for sim
__device__ float g_sim[B * P];          // combined similarity (written by k5)
__device__ int   g_counts[P];           // vote bincount
__device__ int   g_mid[TOPK];           // winning prompt ids

__device__ __forceinline__ float4 f4max(float4 a, float4 b) {
    return make_float4(fmaxf(a.x, b.x), fmaxf(a.y, b.y),
                       fmaxf(a.z, b.z), fmaxf(a.w, b.w));
}
__device__ __forceinline__ float4 f4add(float4 a, float4 b) {
    return make_float4(a.x + b.x, a.y + b.y, a.z + b.z, a.w + b.w);
}

// ---------------- K1: partial max over token chunks (HBM-bound) -------------
__global__ __launch_bounds__(192) void k1_maxpart(const float* __restrict__ x) {
    int blk = blockIdx.x;            // b * NCH + ch  (1024 blocks)
    int b   = blk >> 4;
    int ch  = blk & (NCH - 1);
    int tid = threadIdx.x;           // 0..191

    if (blk == 0) {                  // re-zero vote counts every graph replay
        for (int i = tid; i < P; i += 192) g_counts[i] = 0;
    }

    const float4* xp = reinterpret_cast<const float4*>(x)
                     + (size_t)(b * T + ch * CHUNK) * D4 + tid;
    float4 a0 = xp[0 * D4];
    float4 a1 = xp[1 * D4];
    float4 a2 = xp[2 * D4];
    float4 a3 = xp[3 * D4];
#pragma unroll 4
    for (int t = 4; t < CHUNK; t += 4) {
        a0 = f4max(a0, xp[(t + 0) * D4]);
        a1 = f4max(a1, xp[(t + 1) * D4]);
        a2 = f4max(a2, xp[(t + 2) * D4]);
        a3 = f4max(a3, xp[(t + 3) * D4]);
    }
    float4 m = f4max(f4max(a0, a1), f4max(a2, a3));
    reinterpret_cast<float4*>(g_part)[(size_t)blk * D4 + tid] = m;
}

// ---------------- K2: finalize max over chunks -------------------------------
__global__ __launch_bounds__(192) void k2_maxfin() {
    int b   = blockIdx.x;
    int tid = threadIdx.x;           // 0..191
    const float4* pp = reinterpret_cast<const float4*>(g_part)
                     + (size_t)b * NCH * D4 + tid;
    float4 m = pp[0];
#pragma unroll
    for (int ch = 1; ch < NCH; ch++) m = f4max(m, pp[ch * D4]);
    reinterpret_cast<float4*>(g_xmean)[b * D4 + tid] = m;
}

// ---------------- k_pnorm: l2-normalize prompts ------------------------------
__global__ __launch_bounds__(192) void k_pnorm(const float* __restrict__ prompt) {
    int r   = blockIdx.x;
    int tid = threadIdx.x;           // 0..191
    float4 v = reinterpret_cast<const float4*>(prompt)[r * D4 + tid];
    float s = v.x * v.x + v.y * v.y + v.z * v.z + v.w * v.w;
#pragma unroll
    for (int o = 16; o; o >>= 1) s += __shfl_xor_sync(0xffffffffu, s, o);
    __shared__ float ws[6];
    if ((tid & 31) == 0) ws[tid >> 5] = s;
    __syncthreads();
    float tot = ws[0] + ws[1] + ws[2] + ws[3] + ws[4] + ws[5];
    float sc  = rsqrtf(fmaxf(tot, 1e-12f));
    v.x *= sc; v.y *= sc; v.z *= sc; v.w *= sc;
    reinterpret_cast<float4*>(g_pnorm)[r * D4 + tid] = v;
}

// ---------------- K3p: split-K partial proj, x & W staged in SMEM -----------
// grid = (D/OC) * KS = 96*8 = 768 blocks of 256; smem ~29KB -> ~7 blocks/SM
__global__ __launch_bounds__(256) void k3p(const float* __restrict__ W) {
    __shared__ float xs[B * XSTR];     // 64 x 100 floats = 25.6KB
    __shared__ float ws[OC * XSTR];    // 8 x 100 floats
    int ot = blockIdx.x >> 3;          // 0..95
    int ks = blockIdx.x & 7;           // 0..7
    int o0 = ot * OC;
    int k4 = ks * KC4;                 // float4 offset into K
    int tid = threadIdx.x;

    for (int idx = tid; idx < B * KC4; idx += 256) {
        int b = idx / KC4, i = idx % KC4;
        float4 v = reinterpret_cast<const float4*>(g_xmean)[b * D4 + k4 + i];
        *reinterpret_cast<float4*>(&xs[b * XSTR + i * 4]) = v;
    }
    for (int idx = tid; idx < OC * KC4; idx += 256) {
        int o = idx / KC4, i = idx % KC4;
        float4 v = reinterpret_cast<const float4*>(W)[(o0 + o) * D4 + k4 + i];
        *reinterpret_cast<float4*>(&ws[o * XSTR + i * 4]) = v;
    }
    __syncthreads();

    int ol = tid & (OC - 1);
    int b0 = tid >> 3;
#pragma unroll
    for (int rep = 0; rep < 2; rep++) {
        int b = b0 + rep * 32;
        const float* xr = &xs[b * XSTR];
        const float* wr = &ws[ol * XSTR];
        float4 acc = make_float4(0.f, 0.f, 0.f, 0.f);
#pragma unroll
        for (int i = 0; i < KC4; i++) {
            float4 a = *reinterpret_cast<const float4*>(xr + i * 4);
            float4 w = *reinterpret_cast<const float4*>(wr + i * 4);
            acc.x += a.x * w.x; acc.y += a.y * w.y;
            acc.z += a.z * w.z; acc.w += a.w * w.w;
        }
        g_p3[ks][b][o0 + ol] = acc.x + acc.y + acc.z + acc.w;
    }
}

// ---------------- K3c: combine split-K partials + l2-normalize ---------------
__global__ __launch_bounds__(192) void k3c_xnorm() {
    int b   = blockIdx.x;
    int tid = threadIdx.x;           // 0..191
    float4 v = reinterpret_cast<const float4*>(g_p3[0][b])[tid];
#pragma unroll
    for (int ks = 1; ks < KS; ks++)
        v = f4add(v, reinterpret_cast<const float4*>(g_p3[ks][b])[tid]);
    float s = v.x * v.x + v.y * v.y + v.z * v.z + v.w * v.w;
#pragma unroll
    for (int o = 16; o; o >>= 1) s += __shfl_xor_sync(0xffffffffu, s, o);
    __shared__ float wsm[6];
    if ((tid & 31) == 0) wsm[tid >> 5] = s;
    __syncthreads();
    float tot = wsm[0] + wsm[1] + wsm[2] + wsm[3] + wsm[4] + wsm[5];
    float sc  = rsqrtf(fmaxf(tot, 1e-12f));
    v.x *= sc; v.y *= sc; v.z *= sc; v.w *= sc;
    reinterpret_cast<float4*>(g_xnorm)[b * D4 + tid] = v;
}

// ---------------- K4p: split-K partial similarity ---------------------------
// grid = (P/OC) * KS = 128*8 = 1024 blocks of 256
__global__ __launch_bounds__(256) void k4p() {
    __shared__ float xs[B * XSTR];
    __shared__ float ps[OC * XSTR];
    int pt = blockIdx.x >> 3;          // 0..127
    int ks = blockIdx.x & 7;
    int p0 = pt * OC;
    int k4 = ks * KC4;
    int tid = threadIdx.x;

    for (int idx = tid; idx < B * KC4; idx += 256) {
        int b = idx / KC4, i = idx % KC4;
        float4 v = reinterpret_cast<const float4*>(g_xnorm)[b * D4 + k4 + i];
        *reinterpret_cast<float4*>(&xs[b * XSTR + i * 4]) = v;
    }
    for (int idx = tid; idx < OC * KC4; idx += 256) {
        int p = idx / KC4, i = idx % KC4;
        float4 v = reinterpret_cast<const float4*>(g_pnorm)[(p0 + p) * D4 + k4 + i];
        *reinterpret_cast<float4*>(&ps[p * XSTR + i * 4]) = v;
    }
    __syncthreads();

    int pl = tid & (OC - 1);
    int b0 = tid >> 3;
#pragma unroll
    for (int rep = 0; rep < 2; rep++) {
        int b = b0 + rep * 32;
        const float* xr = &xs[b * XSTR];
        const float* pr = &ps[pl * XSTR];
        float4 acc = make_float4(0.f, 0.f, 0.f, 0.f);
#pragma unroll
        for (int i = 0; i < KC4; i++) {
            float4 a = *reinterpret_cast<const float4*>(xr + i * 4);
            float4 w = *reinterpret_cast<const float4*>(pr + i * 4);
            acc.x += a.x * w.x; acc.y += a.y * w.y;
            acc.z += a.z * w.z; acc.w += a.w * w.w;
        }
        g_p4[ks][b][p0 + pl] = acc.x + acc.y + acc.z + acc.w;
    }
}

// ---------------- K5: combine sim partials + per-row top-8 + bincount -------
__global__ __launch_bounds__(256) void k5_top8() {
    __shared__ float sv[P];
    __shared__ float bv[256];
    __shared__ int   bi[256];
    int b   = blockIdx.x;
    int tid = threadIdx.x;           // 0..255
    // combine 8 split-K partials while loading; also publish to g_sim for k6
    for (int i4 = tid; i4 < P / 4; i4 += 256) {
        float4 v = reinterpret_cast<const float4*>(g_p4[0][b])[i4];
#pragma unroll
        for (int ks = 1; ks < KS; ks++)
            v = f4add(v, reinterpret_cast<const float4*>(g_p4[ks][b])[i4]);
        *reinterpret_cast<float4*>(&sv[i4 * 4]) = v;
        reinterpret_cast<float4*>(g_sim)[b * (P / 4) + i4] = v;
    }
    __syncthreads();
    for (int r = 0; r < TOPK; r++) {
        float best = -3.4e38f; int idx = 0;
        for (int j = tid; j < P; j += 256) {   // ascending j: strict '>' keeps lowest idx
            float v = sv[j];
            if (v > best) { best = v; idx = j; }
        }
        bv[tid] = best; bi[tid] = idx;
        __syncthreads();
        for (int s = 128; s > 0; s >>= 1) {
            if (tid < s) {
                float v2 = bv[tid + s]; int i2 = bi[tid + s];
                if (v2 > bv[tid] || (v2 == bv[tid] && i2 < bi[tid])) {
                    bv[tid] = v2; bi[tid] = i2;
                }
            }
            __syncthreads();
        }
        if (tid == 0) {
            atomicAdd(&g_counts[bi[0]], 1);
            sv[bi[0]] = -3.4e38f;
        }
        __syncthreads();
    }
}

// ---------------- K6: vote top-8 of counts + reduce_sim ----------------------
__global__ __launch_bounds__(256) void k6_vote(float* __restrict__ out) {
    __shared__ int   cv[P];
    __shared__ int   bvv[256];
    __shared__ int   bii[256];
    __shared__ int   ms[TOPK];
    __shared__ float wsum[8];
    int tid = threadIdx.x;           // 0..255
    for (int i = tid; i < P; i += 256) cv[i] = g_counts[i];
    __syncthreads();
    for (int r = 0; r < TOPK; r++) {
        int best = -1, idx = 0;
        for (int j = tid; j < P; j += 256) {
            int v = cv[j];
            if (v > best) { best = v; idx = j; }
        }
        bvv[tid] = best; bii[tid] = idx;
        __syncthreads();
        for (int s = 128; s > 0; s >>= 1) {
            if (tid < s) {
                if (bvv[tid + s] > bvv[tid] ||
                    (bvv[tid + s] == bvv[tid] && bii[tid + s] < bii[tid])) {
                    bvv[tid] = bvv[tid + s]; bii[tid] = bii[tid + s];
                }
            }
            __syncthreads();
        }
        if (tid == 0) { ms[r] = bii[0]; g_mid[r] = bii[0]; cv[bii[0]] = -1; }
        __syncthreads();
    }
    // reduce_sim = sum_{b,j} sim[b, mid[j]] / B
    float s = 0.f;
    for (int t = tid; t < B * TOPK; t += 256) {
        int b = t >> 3, j = t & 7;
        s += g_sim[b * P + ms[j]];
    }
#pragma unroll
    for (int o = 16; o; o >>= 1) s += __shfl_xor_sync(0xffffffffu, s, o);
    if ((tid & 31) == 0) wsum[tid >> 5] = s;
    __syncthreads();
    if (tid == 0) {
        float tot = 0.f;
#pragma unroll
        for (int w = 0; w < 8; w++) tot += wsum[w];
        out[0] = tot / (float)B;
    }
}

// ---------------- K7: gather batched_prompt ----------------------------------
__global__ __launch_bounds__(192) void k7_gather(const float* __restrict__ prompt,
                                                 float* __restrict__ out) {
    int blk = blockIdx.x;            // b*8 + j, 512 blocks
    int j   = blk & 7;
    int pid = g_mid[j];
    int tid = threadIdx.x;           // 0..191
    const float* src = prompt + (size_t)pid * D;
    float* dst = out + 1 + (size_t)blk * D;   // out[0] = reduce_sim
#pragma unroll
    for (int k = 0; k < 4; k++) dst[tid + k * 192] = src[tid + k * 192];
}

// ---------------- launch ------------------------------------------------------
extern "C" void kernel_launch(void* const* d_in, const int* in_sizes, int n_in,
                              void* d_out, int out_size) {
    const float* x      = (const float*)d_in[0];
    const float* prompt = (const float*)d_in[1];
    const float* W      = (const float*)d_in[2];
    float* out          = (float*)d_out;

    k1_maxpart<<<B * NCH, 192>>>(x);
    k2_maxfin<<<B, 192>>>();
    k_pnorm<<<P, 192>>>(prompt);
    k3p<<<(D / OC) * KS, 256>>>(W);
    k3c_xnorm<<<B, 192>>>();
    k4p<<<(P / OC) * KS, 256>>>();
    k5_top8<<<B, 256>>>();
    k6_vote<<<1, 256>>>(out);
    k7_gather<<<B * TOPK, 192>>>(prompt, out);
}

// round 10
// speedup vs baseline: 1.2812x; 1.0043x over previous
#include <cuda_runtime.h>

#define B 64
#define T 2048
#define D 768
#define P 1024
#define TOPK 8
#define NCH 16
#define CHUNK 128     // T / NCH
#define D4 192        // D / 4 (float4 per row)
#define KSPL 12       // split-K factor (K=64 per split)
#define KC 64         // K floats per split
#define KC4 16        // float4 per split
#define TSTR 68       // smem tile row stride (floats): 64 + 4 pad

// ---------------- scratch (device globals; no allocations allowed) ----------
__device__ float g_part[B * NCH * D];   // token-max partials (3 MB)
__device__ float g_xmean[B * D];        // max over tokens
__device__ float g_pnorm[P * D];        // l2-normalized prompts
__device__ float g_xnorm[B * D];        // normalized x_proj
__device__ float g_p3[KSPL][B][D];      // split-K partials for proj (2.25 MB)
__device__ float g_p4[KSPL][B][P];      // split-K partials for sim (3 MB)
__device__ float g_sim[B * P];          // combined similarity (written by k5)
__device__ int   g_counts[P];           // vote bincount
__device__ int   g_mid[TOPK];           // winning prompt ids

__device__ __forceinline__ float4 f4max(float4 a, float4 b) {
    return make_float4(fmaxf(a.x, b.x), fmaxf(a.y, b.y),
                       fmaxf(a.z, b.z), fmaxf(a.w, b.w));
}
__device__ __forceinline__ float4 f4add(float4 a, float4 b) {
    return make_float4(a.x + b.x, a.y + b.y, a.z + b.z, a.w + b.w);
}

// ---------------- K1: partial max over token chunks (HBM-bound) -------------
__global__ __launch_bounds__(192) void k1_maxpart(const float* __restrict__ x) {
    int blk = blockIdx.x;            // b * NCH + ch  (1024 blocks)
    int b   = blk >> 4;
    int ch  = blk & (NCH - 1);
    int tid = threadIdx.x;           // 0..191

    if (blk == 0) {                  // re-zero vote counts every graph replay
        for (int i = tid; i < P; i += 192) g_counts[i] = 0;
    }

    const float4* xp = reinterpret_cast<const float4*>(x)
                     + (size_t)(b * T + ch * CHUNK) * D4 + tid;
    float4 a0 = xp[0 * D4];
    float4 a1 = xp[1 * D4];
    float4 a2 = xp[2 * D4];
    float4 a3 = xp[3 * D4];
#pragma unroll 4
    for (int t = 4; t < CHUNK; t += 4) {
        a0 = f4max(a0, xp[(t + 0) * D4]);
        a1 = f4max(a1, xp[(t + 1) * D4]);
        a2 = f4max(a2, xp[(t + 2) * D4]);
        a3 = f4max(a3, xp[(t + 3) * D4]);
    }
    float4 m = f4max(f4max(a0, a1), f4max(a2, a3));
    reinterpret_cast<float4*>(g_part)[(size_t)blk * D4 + tid] = m;
}

// ---------------- K2: finalize max over chunks -------------------------------
__global__ __launch_bounds__(192) void k2_maxfin() {
    int b   = blockIdx.x;
    int tid = threadIdx.x;           // 0..191
    const float4* pp = reinterpret_cast<const float4*>(g_part)
                     + (size_t)b * NCH * D4 + tid;
    float4 m = pp[0];
#pragma unroll
    for (int ch = 1; ch < NCH; ch++) m = f4max(m, pp[ch * D4]);
    reinterpret_cast<float4*>(g_xmean)[b * D4 + tid] = m;
}

// ---------------- k_pnorm: l2-normalize prompts ------------------------------
__global__ __launch_bounds__(192) void k_pnorm(const float* __restrict__ prompt) {
    int r   = blockIdx.x;
    int tid = threadIdx.x;           // 0..191
    float4 v = reinterpret_cast<const float4*>(prompt)[r * D4 + tid];
    float s = v.x * v.x + v.y * v.y + v.z * v.z + v.w * v.w;
#pragma unroll
    for (int o = 16; o; o >>= 1) s += __shfl_xor_sync(0xffffffffu, s, o);
    __shared__ float ws[6];
    if ((tid & 31) == 0) ws[tid >> 5] = s;
    __syncthreads();
    float tot = ws[0] + ws[1] + ws[2] + ws[3] + ws[4] + ws[5];
    float sc  = rsqrtf(fmaxf(tot, 1e-12f));
    v.x *= sc; v.y *= sc; v.z *= sc; v.w *= sc;
    reinterpret_cast<float4*>(g_pnorm)[r * D4 + tid] = v;
}

// ---------------- register-tiled split-K matmul body -------------------------
// Computes out[ks][b][o0+o] = sum_{k in split ks} lhs[b][k] * rhs[o0+o][k]
// Block: 256 threads; tile = 64 b x 64 o x 64 k. Thread computes 4b x 4o.
__device__ __forceinline__ void mm_tile_body(
    const float* __restrict__ lhs,   // [B][D] row-major
    const float* __restrict__ rhs,   // [N][D] row-major
    float* __restrict__ outp,        // &out[ks][0][0], row stride = ncols
    int ncols, int o0, int k0, int tid)
{
    __shared__ float xs[64 * TSTR];
    __shared__ float ws[64 * TSTR];
    int k4 = k0 / 4;

    // stage tiles: 64 rows x 16 float4 each
    for (int idx = tid; idx < 64 * KC4; idx += 256) {
        int row = idx >> 4, col = idx & 15;
        float4 v = reinterpret_cast<const float4*>(lhs)[row * D4 + k4 + col];
        *reinterpret_cast<float4*>(&xs[row * TSTR + col * 4]) = v;
    }
    for (int idx = tid; idx < 64 * KC4; idx += 256) {
        int row = idx >> 4, col = idx & 15;
        float4 v = reinterpret_cast<const float4*>(rhs)[(o0 + row) * D4 + k4 + col];
        *reinterpret_cast<float4*>(&ws[row * TSTR + col * 4]) = v;
    }
    __syncthreads();

    int tx = tid & 15;               // o-group
    int ty = tid >> 4;               // b-group
    const float* xbase = &xs[(ty * 4) * TSTR];
    const float* wbase = &ws[(tx * 4) * TSTR];

    float acc[4][4];
#pragma unroll
    for (int i = 0; i < 4; i++)
#pragma unroll
        for (int j = 0; j < 4; j++) acc[i][j] = 0.f;

#pragma unroll 4
    for (int i = 0; i < KC4; i++) {
        float4 xa[4], wb[4];
#pragma unroll
        for (int j = 0; j < 4; j++)
            xa[j] = *reinterpret_cast<const float4*>(xbase + j * TSTR + i * 4);
#pragma unroll
        for (int j = 0; j < 4; j++)
            wb[j] = *reinterpret_cast<const float4*>(wbase + j * TSTR + i * 4);
#pragma unroll
        for (int bj = 0; bj < 4; bj++)
#pragma unroll
            for (int oj = 0; oj < 4; oj++) {
                acc[bj][oj] += xa[bj].x * wb[oj].x + xa[bj].y * wb[oj].y
                             + xa[bj].z * wb[oj].z + xa[bj].w * wb[oj].w;
            }
    }

#pragma unroll
    for (int bj = 0; bj < 4; bj++) {
        int b = ty * 4 + bj;
#pragma unroll
        for (int oj = 0; oj < 4; oj++) {
            int o = o0 + tx * 4 + oj;
            outp[b * ncols + o] = acc[bj][oj];
        }
    }
}

// ---------------- K3p: proj partials. grid = 12 o-tiles * 12 ks = 144 -------
__global__ __launch_bounds__(256) void k3p(const float* __restrict__ W) {
    int ot = blockIdx.x / KSPL;
    int ks = blockIdx.x % KSPL;
    mm_tile_body(g_xmean, W, &g_p3[ks][0][0], D, ot * 64, ks * KC, threadIdx.x);
}

// ---------------- K3c: combine split-K partials + l2-normalize ---------------
__global__ __launch_bounds__(192) void k3c_xnorm() {
    int b   = blockIdx.x;
    int tid = threadIdx.x;           // 0..191
    float4 v = reinterpret_cast<const float4*>(g_p3[0][b])[tid];
#pragma unroll
    for (int ks = 1; ks < KSPL; ks++)
        v = f4add(v, reinterpret_cast<const float4*>(g_p3[ks][b])[tid]);
    float s = v.x * v.x + v.y * v.y + v.z * v.z + v.w * v.w;
#pragma unroll
    for (int o = 16; o; o >>= 1) s += __shfl_xor_sync(0xffffffffu, s, o);
    __shared__ float wsm[6];
    if ((tid & 31) == 0) wsm[tid >> 5] = s;
    __syncthreads();
    float tot = wsm[0] + wsm[1] + wsm[2] + wsm[3] + wsm[4] + wsm[5];
    float sc  = rsqrtf(fmaxf(tot, 1e-12f));
    v.x *= sc; v.y *= sc; v.z *= sc; v.w *= sc;
    reinterpret_cast<float4*>(g_xnorm)[b * D4 + tid] = v;
}

// ---------------- K4p: sim partials. grid = 16 p-tiles * 12 ks = 192 --------
__global__ __launch_bounds__(256) void k4p() {
    int pt = blockIdx.x / KSPL;
    int ks = blockIdx.x % KSPL;
    mm_tile_body(g_xnorm, g_pnorm, &g_p4[ks][0][0], P, pt * 64, ks * KC, threadIdx.x);
}

// ---------------- K5: combine sim partials + per-row top-8 + bincount -------
__global__ __launch_bounds__(256) void k5_top8() {
    __shared__ float sv[P];
    __shared__ float bv[256];
    __shared__ int   bi[256];
    int b   = blockIdx.x;
    int tid = threadIdx.x;           // 0..255
    // combine split-K partials while loading; also publish to g_sim for k6
    for (int i4 = tid; i4 < P / 4; i4 += 256) {
        float4 v = reinterpret_cast<const float4*>(g_p4[0][b])[i4];
#pragma unroll
        for (int ks = 1; ks < KSPL; ks++)
            v = f4add(v, reinterpret_cast<const float4*>(g_p4[ks][b])[i4]);
        *reinterpret_cast<float4*>(&sv[i4 * 4]) = v;
        reinterpret_cast<float4*>(g_sim)[b * (P / 4) + i4] = v;
    }
    __syncthreads();
    for (int r = 0; r < TOPK; r++) {
        float best = -3.4e38f; int idx = 0;
        for (int j = tid; j < P; j += 256) {   // ascending j: strict '>' keeps lowest idx
            float v = sv[j];
            if (v > best) { best = v; idx = j; }
        }
        bv[tid] = best; bi[tid] = idx;
        __syncthreads();
        for (int s = 128; s > 0; s >>= 1) {
            if (tid < s) {
                float v2 = bv[tid + s]; int i2 = bi[tid + s];
                if (v2 > bv[tid] || (v2 == bv[tid] && i2 < bi[tid])) {
                    bv[tid] = v2; bi[tid] = i2;
                }
            }
            __syncthreads();
        }
        if (tid == 0) {
            atomicAdd(&g_counts[bi[0]], 1);
            sv[bi[0]] = -3.4e38f;
        }
        __syncthreads();
    }
}

// ---------------- K6: vote top-8 of counts + reduce_sim ----------------------
__global__ __launch_bounds__(256) void k6_vote(float* __restrict__ out) {
    __shared__ int   cv[P];
    __shared__ int   bvv[256];
    __shared__ int   bii[256];
    __shared__ int   ms[TOPK];
    __shared__ float wsum[8];
    int tid = threadIdx.x;           // 0..255
    for (int i = tid; i < P; i += 256) cv[i] = g_counts[i];
    __syncthreads();
    for (int r = 0; r < TOPK; r++) {
        int best = -1, idx = 0;
        for (int j = tid; j < P; j += 256) {
            int v = cv[j];
            if (v > best) { best = v; idx = j; }
        }
        bvv[tid] = best; bii[tid] = idx;
        __syncthreads();
        for (int s = 128; s > 0; s >>= 1) {
            if (tid < s) {
                if (bvv[tid + s] > bvv[tid] ||
                    (bvv[tid + s] == bvv[tid] && bii[tid + s] < bii[tid])) {
                    bvv[tid] = bvv[tid + s]; bii[tid] = bii[tid + s];
                }
            }
            __syncthreads();
        }
        if (tid == 0) { ms[r] = bii[0]; g_mid[r] = bii[0]; cv[bii[0]] = -1; }
        __syncthreads();
    }
    // reduce_sim = sum_{b,j} sim[b, mid[j]] / B
    float s = 0.f;
    for (int t = tid; t < B * TOPK; t += 256) {
        int b = t >> 3, j = t & 7;
        s += g_sim[b * P + ms[j]];
    }
#pragma unroll
    for (int o = 16; o; o >>= 1) s += __shfl_xor_sync(0xffffffffu, s, o);
    if ((tid & 31) == 0) wsum[tid >> 5] = s;
    __syncthreads();
    if (tid == 0) {
        float tot = 0.f;
#pragma unroll
        for (int w = 0; w < 8; w++) tot += wsum[w];
        out[0] = tot / (float)B;
    }
}

// ---------------- K7: gather batched_prompt ----------------------------------
__global__ __launch_bounds__(192) void k7_gather(const float* __restrict__ prompt,
                                                 float* __restrict__ out) {
    int blk = blockIdx.x;            // b*8 + j, 512 blocks
    int j   = blk & 7;
    int pid = g_mid[j];
    int tid = threadIdx.x;           // 0..191
    const float* src = prompt + (size_t)pid * D;
    float* dst = out + 1 + (size_t)blk * D;   // out[0] = reduce_sim
#pragma unroll
    for (int k = 0; k < 4; k++) dst[tid + k * 192] = src[tid + k * 192];
}

// ---------------- launch ------------------------------------------------------
extern "C" void kernel_launch(void* const* d_in, const int* in_sizes, int n_in,
                              void* d_out, int out_size) {
    const float* x      = (const float*)d_in[0];
    const float* prompt = (const float*)d_in[1];
    const float* W      = (const float*)d_in[2];
    float* out          = (float*)d_out;

    k1_maxpart<<<B * NCH, 192>>>(x);
    k2_maxfin<<<B, 192>>>();
    k_pnorm<<<P, 192>>>(prompt);
    k3p<<<(D / 64) * KSPL, 256>>>(W);
    k3c_xnorm<<<B, 192>>>();
    k4p<<<(P / 64) * KSPL, 256>>>();
    k5_top8<<<B, 256>>>();
    k6_vote<<<1, 256>>>(out);
    k7_gather<<<B * TOPK, 192>>>(prompt, out);
}

// round 13
// speedup vs baseline: 1.3397x; 1.0457x over previous
#include <cuda_runtime.h>

#define B 64
#define T 2048
#define D 768
#define P 1024
#define TOPK 8
#define NCH 16
#define CHUNK 128     // T / NCH
#define D4 192        // D / 4 (float4 per row)
#define KSPL 24       // split-K factor (K=32 per split)
#define KC 32         // K floats per split
#define KC4 8         // float4 per split
#define TSTR 36       // smem tile row stride (floats): 32 + 4 pad (shift-1 bank groups)

// ---------------- scratch (device globals; no allocations allowed) ----------
__device__ float g_part[B * NCH * D];   // token-max partials (3 MB)
__device__ float g_xmean[B * D];        // max over tokens
__device__ float g_pnorm[P * D];        // l2-normalized prompts
__device__ float g_xnorm[B * D];        // normalized x_proj
__device__ float g_p3[KSPL][B][D];      // split-K partials for proj (4.7 MB)
__device__ float g_p4[KSPL][B][P];      // split-K partials for sim (6.3 MB)
__device__ float g_sim[B * P];          // combined similarity (written by k5)
__device__ int   g_counts[P];           // vote bincount
__device__ int   g_mid[TOPK];           // winning prompt ids

__device__ __forceinline__ float4 f4max(float4 a, float4 b) {
    return make_float4(fmaxf(a.x, b.x), fmaxf(a.y, b.y),
                       fmaxf(a.z, b.z), fmaxf(a.w, b.w));
}
__device__ __forceinline__ float4 f4add(float4 a, float4 b) {
    return make_float4(a.x + b.x, a.y + b.y, a.z + b.z, a.w + b.w);
}

// ---------------- K1: partial max over token chunks (HBM-bound) -------------
__global__ __launch_bounds__(192) void k1_maxpart(const float* __restrict__ x) {
    int blk = blockIdx.x;            // b * NCH + ch  (1024 blocks)
    int b   = blk >> 4;
    int ch  = blk & (NCH - 1);
    int tid = threadIdx.x;           // 0..191

    if (blk == 0) {                  // re-zero vote counts every graph replay
        for (int i = tid; i < P; i += 192) g_counts[i] = 0;
    }

    const float4* xp = reinterpret_cast<const float4*>(x)
                     + (size_t)(b * T + ch * CHUNK) * D4 + tid;
    float4 a0 = xp[0 * D4];
    float4 a1 = xp[1 * D4];
    float4 a2 = xp[2 * D4];
    float4 a3 = xp[3 * D4];
#pragma unroll 4
    for (int t = 4; t < CHUNK; t += 4) {
        a0 = f4max(a0, xp[(t + 0) * D4]);
        a1 = f4max(a1, xp[(t + 1) * D4]);
        a2 = f4max(a2, xp[(t + 2) * D4]);
        a3 = f4max(a3, xp[(t + 3) * D4]);
    }
    float4 m = f4max(f4max(a0, a1), f4max(a2, a3));
    reinterpret_cast<float4*>(g_part)[(size_t)blk * D4 + tid] = m;
}

// ---------------- K2: finalize max over chunks -------------------------------
__global__ __launch_bounds__(192) void k2_maxfin() {
    int b   = blockIdx.x;
    int tid = threadIdx.x;           // 0..191
    const float4* pp = reinterpret_cast<const float4*>(g_part)
                     + (size_t)b * NCH * D4 + tid;
    float4 m = pp[0];
#pragma unroll
    for (int ch = 1; ch < NCH; ch++) m = f4max(m, pp[ch * D4]);
    reinterpret_cast<float4*>(g_xmean)[b * D4 + tid] = m;
}

// ---------------- k_pnorm: l2-normalize prompts ------------------------------
__global__ __launch_bounds__(192) void k_pnorm(const float* __restrict__ prompt) {
    int r   = blockIdx.x;
    int tid = threadIdx.x;           // 0..191
    float4 v = reinterpret_cast<const float4*>(prompt)[r * D4 + tid];
    float s = v.x * v.x + v.y * v.y + v.z * v.z + v.w * v.w;
#pragma unroll
    for (int o = 16; o; o >>= 1) s += __shfl_xor_sync(0xffffffffu, s, o);
    __shared__ float ws[6];
    if ((tid & 31) == 0) ws[tid >> 5] = s;
    __syncthreads();
    float tot = ws[0] + ws[1] + ws[2] + ws[3] + ws[4] + ws[5];
    float sc  = rsqrtf(fmaxf(tot, 1e-12f));
    v.x *= sc; v.y *= sc; v.z *= sc; v.w *= sc;
    reinterpret_cast<float4*>(g_pnorm)[r * D4 + tid] = v;
}

// ---------------- register-tiled split-K matmul body (v2) --------------------
// out[ks][b][o0+o] = sum_{k in split} lhs[b][k] * rhs[o0+o][k]
// 128 threads; tile 64b x 32o x 32k; thread computes 4b x 4o with STRIDED rows:
//   b = ty + 16*bj (ty 0..15), o = o0 + tx + 8*oj (tx 0..7)
// -> simultaneous LDS rows within a warp are consecutive -> distinct bank groups.
__device__ __forceinline__ void mm_tile_body(
    const float* __restrict__ lhs,   // [*, D] row-major
    const float* __restrict__ rhs,   // [*, D] row-major
    float* __restrict__ outp,        // &out[ks][0][0], row stride = ncols
    int ncols, int o0, int k0, int tid)
{
    __shared__ float xs[64 * TSTR];  // 64 b-rows x 32k (+pad)
    __shared__ float ws[32 * TSTR];  // 32 o-rows x 32k (+pad)
    int k4 = k0 >> 2;

    // stage: xs 64 rows x 8 float4 (4/thread), ws 32 x 8 (2/thread)
    for (int idx = tid; idx < 64 * KC4; idx += 128) {
        int row = idx >> 3, col = idx & 7;
        float4 v = reinterpret_cast<const float4*>(lhs)[row * D4 + k4 + col];
        *reinterpret_cast<float4*>(&xs[row * TSTR + col * 4]) = v;
    }
    for (int idx = tid; idx < 32 * KC4; idx += 128) {
        int row = idx >> 3, col = idx & 7;
        float4 v = reinterpret_cast<const float4*>(rhs)[(o0 + row) * D4 + k4 + col];
        *reinterpret_cast<float4*>(&ws[row * TSTR + col * 4]) = v;
    }
    __syncthreads();

    int tx = tid & 7;                // o-group
    int ty = tid >> 3;               // b-group (0..15)

    float acc[4][4];
#pragma unroll
    for (int i = 0; i < 4; i++)
#pragma unroll
        for (int j = 0; j < 4; j++) acc[i][j] = 0.f;

#pragma unroll
    for (int i = 0; i < KC4; i++) {
        float4 xa[4], wb[4];
#pragma unroll
        for (int j = 0; j < 4; j++)
            xa[j] = *reinterpret_cast<const float4*>(&xs[(ty + 16 * j) * TSTR + i * 4]);
#pragma unroll
        for (int j = 0; j < 4; j++)
            wb[j] = *reinterpret_cast<const float4*>(&ws[(tx + 8 * j) * TSTR + i * 4]);
#pragma unroll
        for (int bj = 0; bj < 4; bj++)
#pragma unroll
            for (int oj = 0; oj < 4; oj++) {
                acc[bj][oj] += xa[bj].x * wb[oj].x + xa[bj].y * wb[oj].y
                             + xa[bj].z * wb[oj].z + xa[bj].w * wb[oj].w;
            }
    }

#pragma unroll
    for (int bj = 0; bj < 4; bj++) {
        int b = ty + 16 * bj;
#pragma unroll
        for (int oj = 0; oj < 4; oj++) {
            int o = o0 + tx + 8 * oj;
            outp[b * ncols + o] = acc[bj][oj];
        }
    }
}

// ---------------- K3p: proj partials. grid = 24 o-tiles * 24 ks = 576 -------
__global__ __launch_bounds__(128) void k3p(const float* __restrict__ W) {
    int ot = blockIdx.x / KSPL;
    int ks = blockIdx.x % KSPL;
    mm_tile_body(g_xmean, W, &g_p3[ks][0][0], D, ot * 32, ks * KC, threadIdx.x);
}

// ---------------- K3c: combine split-K partials + l2-normalize ---------------
__global__ __launch_bounds__(192) void k3c_xnorm() {
    int b   = blockIdx.x;
    int tid = threadIdx.x;           // 0..191
    float4 v = reinterpret_cast<const float4*>(g_p3[0][b])[tid];
#pragma unroll
    for (int ks = 1; ks < KSPL; ks++)
        v = f4add(v, reinterpret_cast<const float4*>(g_p3[ks][b])[tid]);
    float s = v.x * v.x + v.y * v.y + v.z * v.z + v.w * v.w;
#pragma unroll
    for (int o = 16; o; o >>= 1) s += __shfl_xor_sync(0xffffffffu, s, o);
    __shared__ float wsm[6];
    if ((tid & 31) == 0) wsm[tid >> 5] = s;
    __syncthreads();
    float tot = wsm[0] + wsm[1] + wsm[2] + wsm[3] + wsm[4] + wsm[5];
    float sc  = rsqrtf(fmaxf(tot, 1e-12f));
    v.x *= sc; v.y *= sc; v.z *= sc; v.w *= sc;
    reinterpret_cast<float4*>(g_xnorm)[b * D4 + tid] = v;
}

// ---------------- K4p: sim partials. grid = 32 p-tiles * 24 ks = 768 --------
__global__ __launch_bounds__(128) void k4p() {
    int pt = blockIdx.x / KSPL;
    int ks = blockIdx.x % KSPL;
    mm_tile_body(g_xnorm, g_pnorm, &g_p4[ks][0][0], P, pt * 32, ks * KC, threadIdx.x);
}

// ---------------- K5: combine sim partials + per-row top-8 + bincount -------
__global__ __launch_bounds__(256) void k5_top8() {
    __shared__ float sv[P];
    __shared__ float bv[256];
    __shared__ int   bi[256];
    int b   = blockIdx.x;
    int tid = threadIdx.x;           // 0..255
    // combine split-K partials while loading; also publish to g_sim for k6
    for (int i4 = tid; i4 < P / 4; i4 += 256) {
        float4 v = reinterpret_cast<const float4*>(g_p4[0][b])[i4];
#pragma unroll
        for (int ks = 1; ks < KSPL; ks++)
            v = f4add(v, reinterpret_cast<const float4*>(g_p4[ks][b])[i4]);
        *reinterpret_cast<float4*>(&sv[i4 * 4]) = v;
        reinterpret_cast<float4*>(g_sim)[b * (P / 4) + i4] = v;
    }
    __syncthreads();
    for (int r = 0; r < TOPK; r++) {
        float best = -3.4e38f; int idx = 0;
        for (int j = tid; j < P; j += 256) {   // ascending j: strict '>' keeps lowest idx
            float v = sv[j];
            if (v > best) { best = v; idx = j; }
        }
        bv[tid] = best; bi[tid] = idx;
        __syncthreads();
        for (int s = 128; s > 0; s >>= 1) {
            if (tid < s) {
                float v2 = bv[tid + s]; int i2 = bi[tid + s];
                if (v2 > bv[tid] || (v2 == bv[tid] && i2 < bi[tid])) {
                    bv[tid] = v2; bi[tid] = i2;
                }
            }
            __syncthreads();
        }
        if (tid == 0) {
            atomicAdd(&g_counts[bi[0]], 1);
            sv[bi[0]] = -3.4e38f;
        }
        __syncthreads();
    }
}

// ---------------- K6: vote top-8 of counts + reduce_sim ----------------------
__global__ __launch_bounds__(256) void k6_vote(float* __restrict__ out) {
    __shared__ int   cv[P];
    __shared__ int   bvv[256];
    __shared__ int   bii[256];
    __shared__ int   ms[TOPK];
    __shared__ float wsum[8];
    int tid = threadIdx.x;           // 0..255
    for (int i = tid; i < P; i += 256) cv[i] = g_counts[i];
    __syncthreads();
    for (int r = 0; r < TOPK; r++) {
        int best = -1, idx = 0;
        for (int j = tid; j < P; j += 256) {
            int v = cv[j];
            if (v > best) { best = v; idx = j; }
        }
        bvv[tid] = best; bii[tid] = idx;
        __syncthreads();
        for (int s = 128; s > 0; s >>= 1) {
            if (tid < s) {
                if (bvv[tid + s] > bvv[tid] ||
                    (bvv[tid + s] == bvv[tid] && bii[tid + s] < bii[tid])) {
                    bvv[tid] = bvv[tid + s]; bii[tid] = bii[tid + s];
                }
            }
            __syncthreads();
        }
        if (tid == 0) { ms[r] = bii[0]; g_mid[r] = bii[0]; cv[bii[0]] = -1; }
        __syncthreads();
    }
    // reduce_sim = sum_{b,j} sim[b, mid[j]] / B
    float s = 0.f;
    for (int t = tid; t < B * TOPK; t += 256) {
        int b = t >> 3, j = t & 7;
        s += g_sim[b * P + ms[j]];
    }
#pragma unroll
    for (int o = 16; o; o >>= 1) s += __shfl_xor_sync(0xffffffffu, s, o);
    if ((tid & 31) == 0) wsum[tid >> 5] = s;
    __syncthreads();
    if (tid == 0) {
        float tot = 0.f;
#pragma unroll
        for (int w = 0; w < 8; w++) tot += wsum[w];
        out[0] = tot / (float)B;
    }
}

// ---------------- K7: gather batched_prompt ----------------------------------
__global__ __launch_bounds__(192) void k7_gather(const float* __restrict__ prompt,
                                                 float* __restrict__ out) {
    int blk = blockIdx.x;            // b*8 + j, 512 blocks
    int j   = blk & 7;
    int pid = g_mid[j];
    int tid = threadIdx.x;           // 0..191
    const float* src = prompt + (size_t)pid * D;
    float* dst = out + 1 + (size_t)blk * D;   // out[0] = reduce_sim
#pragma unroll
    for (int k = 0; k < 4; k++) dst[tid + k * 192] = src[tid + k * 192];
}

// ---------------- launch ------------------------------------------------------
extern "C" void kernel_launch(void* const* d_in, const int* in_sizes, int n_in,
                              void* d_out, int out_size) {
    const float* x      = (const float*)d_in[0];
    const float* prompt = (const float*)d_in[1];
    const float* W      = (const float*)d_in[2];
    float* out          = (float*)d_out;

    k1_maxpart<<<B * NCH, 192>>>(x);
    k2_maxfin<<<B, 192>>>();
    k_pnorm<<<P, 192>>>(prompt);
    k3p<<<(D / 32) * KSPL, 128>>>(W);
    k3c_xnorm<<<B, 192>>>();
    k4p<<<(P / 32) * KSPL, 128>>>();
    k5_top8<<<B, 256>>>();
    k6_vote<<<1, 256>>>(out);
    k7_gather<<<B * TOPK, 192>>>(prompt, out);
}

// round 15
// speedup vs baseline: 1.3842x; 1.0332x over previous
#include <cuda_runtime.h>

#define B 64
#define T 2048
#define D 768
#define P 1024
#define TOPK 8
#define NCH 16
#define CHUNK 128     // T / NCH
#define D4 192        // D / 4 (float4 per row)
#define KSPL 24       // split-K factor (K=32 per split)
#define KC 32         // K floats per split
#define KC4 8         // float4 per split
#define TSTR 36       // smem tile row stride (floats): 32 + 4 pad (shift-1 bank groups)

// ---------------- scratch (device globals; no allocations allowed) ----------
__device__ float g_part[B * NCH * D];   // token-max partials (3 MB)
__device__ float g_xmean[B * D];        // max over tokens
__device__ float g_pnorm[P * D];        // l2-normalized prompts
__device__ float g_xnorm[B * D];        // normalized x_proj
__device__ float g_p3[KSPL][B][D];      // split-K partials for proj
__device__ float g_p4[KSPL][B][P];      // split-K partials for sim
__device__ float g_sim[B * P];          // combined similarity (written by k5)
__device__ int   g_counts[P];           // vote bincount
__device__ int   g_mid[TOPK];           // winning prompt ids

__device__ __forceinline__ float4 f4max(float4 a, float4 b) {
    return make_float4(fmaxf(a.x, b.x), fmaxf(a.y, b.y),
                       fmaxf(a.z, b.z), fmaxf(a.w, b.w));
}
__device__ __forceinline__ float4 f4add(float4 a, float4 b) {
    return make_float4(a.x + b.x, a.y + b.y, a.z + b.z, a.w + b.w);
}

// ---------------- K1: partial max over token chunks (HBM-bound) -------------
__global__ __launch_bounds__(192) void k1_maxpart(const float* __restrict__ x) {
    int blk = blockIdx.x;            // b * NCH + ch  (1024 blocks)
    int b   = blk >> 4;
    int ch  = blk & (NCH - 1);
    int tid = threadIdx.x;           // 0..191

    if (blk == 0) {                  // re-zero vote counts every graph replay
        for (int i = tid; i < P; i += 192) g_counts[i] = 0;
    }

    const float4* xp = reinterpret_cast<const float4*>(x)
                     + (size_t)(b * T + ch * CHUNK) * D4 + tid;
    float4 a0 = xp[0 * D4];
    float4 a1 = xp[1 * D4];
    float4 a2 = xp[2 * D4];
    float4 a3 = xp[3 * D4];
#pragma unroll 4
    for (int t = 4; t < CHUNK; t += 4) {
        a0 = f4max(a0, xp[(t + 0) * D4]);
        a1 = f4max(a1, xp[(t + 1) * D4]);
        a2 = f4max(a2, xp[(t + 2) * D4]);
        a3 = f4max(a3, xp[(t + 3) * D4]);
    }
    float4 m = f4max(f4max(a0, a1), f4max(a2, a3));
    reinterpret_cast<float4*>(g_part)[(size_t)blk * D4 + tid] = m;
}

// ---------------- K2f: fused finalize-max (64 blocks) + pnorm (1024 blocks) -
__global__ __launch_bounds__(192) void k2f(const float* __restrict__ prompt) {
    int blk = blockIdx.x;
    int tid = threadIdx.x;           // 0..191
    if (blk < B) {
        // finalize token max for batch row blk
        const float4* pp = reinterpret_cast<const float4*>(g_part)
                         + (size_t)blk * NCH * D4 + tid;
        float4 m = pp[0];
#pragma unroll
        for (int ch = 1; ch < NCH; ch++) m = f4max(m, pp[ch * D4]);
        reinterpret_cast<float4*>(g_xmean)[blk * D4 + tid] = m;
    } else {
        // l2-normalize prompt row r
        int r = blk - B;
        float4 v = reinterpret_cast<const float4*>(prompt)[r * D4 + tid];
        float s = v.x * v.x + v.y * v.y + v.z * v.z + v.w * v.w;
#pragma unroll
        for (int o = 16; o; o >>= 1) s += __shfl_xor_sync(0xffffffffu, s, o);
        __shared__ float ws[6];
        if ((tid & 31) == 0) ws[tid >> 5] = s;
        __syncthreads();
        float tot = ws[0] + ws[1] + ws[2] + ws[3] + ws[4] + ws[5];
        float sc  = rsqrtf(fmaxf(tot, 1e-12f));
        v.x *= sc; v.y *= sc; v.z *= sc; v.w *= sc;
        reinterpret_cast<float4*>(g_pnorm)[r * D4 + tid] = v;
    }
}

// ---------------- register-tiled split-K matmul body (v3: 256 thr) ----------
// out[ks][b][o0+o] = sum_{k in split} lhs[b][k] * rhs[o0+o][k]
// 256 threads; tile 64b x 32o x 32k; thread computes 2b x 4o:
//   b = ty + 32*bj (ty 0..31, bj<2), o = o0 + tx + 8*oj (tx 0..7, oj<4)
__device__ __forceinline__ void mm_tile_body(
    const float* __restrict__ lhs,   // [*, D] row-major
    const float* __restrict__ rhs,   // [*, D] row-major
    float* __restrict__ outp,        // &out[ks][0][0], row stride = ncols
    int ncols, int o0, int k0, int tid)
{
    __shared__ float xs[64 * TSTR];  // 64 b-rows x 32k (+pad)
    __shared__ float ws[32 * TSTR];  // 32 o-rows x 32k (+pad)
    int k4 = k0 >> 2;

    // stage: xs 64 rows x 8 float4 (2/thread), ws 32 x 8 (1/thread)
    for (int idx = tid; idx < 64 * KC4; idx += 256) {
        int row = idx >> 3, col = idx & 7;
        float4 v = reinterpret_cast<const float4*>(lhs)[row * D4 + k4 + col];
        *reinterpret_cast<float4*>(&xs[row * TSTR + col * 4]) = v;
    }
    for (int idx = tid; idx < 32 * KC4; idx += 256) {
        int row = idx >> 3, col = idx & 7;
        float4 v = reinterpret_cast<const float4*>(rhs)[(o0 + row) * D4 + k4 + col];
        *reinterpret_cast<float4*>(&ws[row * TSTR + col * 4]) = v;
    }
    __syncthreads();

    int tx = tid & 7;                // o-group
    int ty = tid >> 3;               // b-group (0..31)

    float acc[2][4];
#pragma unroll
    for (int i = 0; i < 2; i++)
#pragma unroll
        for (int j = 0; j < 4; j++) acc[i][j] = 0.f;

#pragma unroll
    for (int i = 0; i < KC4; i++) {
        float4 xa[2], wb[4];
#pragma unroll
        for (int j = 0; j < 2; j++)
            xa[j] = *reinterpret_cast<const float4*>(&xs[(ty + 32 * j) * TSTR + i * 4]);
#pragma unroll
        for (int j = 0; j < 4; j++)
            wb[j] = *reinterpret_cast<const float4*>(&ws[(tx + 8 * j) * TSTR + i * 4]);
#pragma unroll
        for (int bj = 0; bj < 2; bj++)
#pragma unroll
            for (int oj = 0; oj < 4; oj++) {
                acc[bj][oj] += xa[bj].x * wb[oj].x + xa[bj].y * wb[oj].y
                             + xa[bj].z * wb[oj].z + xa[bj].w * wb[oj].w;
            }
    }

#pragma unroll
    for (int bj = 0; bj < 2; bj++) {
        int b = ty + 32 * bj;
#pragma unroll
        for (int oj = 0; oj < 4; oj++) {
            int o = o0 + tx + 8 * oj;
            outp[b * ncols + o] = acc[bj][oj];
        }
    }
}

// ---------------- K3p: proj partials. grid = 24 o-tiles * 24 ks = 576 -------
__global__ __launch_bounds__(256) void k3p(const float* __restrict__ W) {
    int ot = blockIdx.x / KSPL;
    int ks = blockIdx.x % KSPL;
    mm_tile_body(g_xmean, W, &g_p3[ks][0][0], D, ot * 32, ks * KC, threadIdx.x);
}

// ---------------- K3c: combine split-K partials + l2-normalize ---------------
__global__ __launch_bounds__(192) void k3c_xnorm() {
    int b   = blockIdx.x;
    int tid = threadIdx.x;           // 0..191
    float4 v = reinterpret_cast<const float4*>(g_p3[0][b])[tid];
#pragma unroll
    for (int ks = 1; ks < KSPL; ks++)
        v = f4add(v, reinterpret_cast<const float4*>(g_p3[ks][b])[tid]);
    float s = v.x * v.x + v.y * v.y + v.z * v.z + v.w * v.w;
#pragma unroll
    for (int o = 16; o; o >>= 1) s += __shfl_xor_sync(0xffffffffu, s, o);
    __shared__ float wsm[6];
    if ((tid & 31) == 0) wsm[tid >> 5] = s;
    __syncthreads();
    float tot = wsm[0] + wsm[1] + wsm[2] + wsm[3] + wsm[4] + wsm[5];
    float sc  = rsqrtf(fmaxf(tot, 1e-12f));
    v.x *= sc; v.y *= sc; v.z *= sc; v.w *= sc;
    reinterpret_cast<float4*>(g_xnorm)[b * D4 + tid] = v;
}

// ---------------- K4p: sim partials. grid = 32 p-tiles * 24 ks = 768 --------
__global__ __launch_bounds__(256) void k4p() {
    int pt = blockIdx.x / KSPL;
    int ks = blockIdx.x % KSPL;
    mm_tile_body(g_xnorm, g_pnorm, &g_p4[ks][0][0], P, pt * 32, ks * KC, threadIdx.x);
}

// ---------------- K5: combine sim partials + per-row top-8 + bincount -------
__global__ __launch_bounds__(256) void k5_top8() {
    __shared__ float sv[P];
    __shared__ float bv[256];
    __shared__ int   bi[256];
    int b   = blockIdx.x;
    int tid = threadIdx.x;           // 0..255
    // combine split-K partials while loading; also publish to g_sim for k6
    for (int i4 = tid; i4 < P / 4; i4 += 256) {
        float4 v = reinterpret_cast<const float4*>(g_p4[0][b])[i4];
#pragma unroll
        for (int ks = 1; ks < KSPL; ks++)
            v = f4add(v, reinterpret_cast<const float4*>(g_p4[ks][b])[i4]);
        *reinterpret_cast<float4*>(&sv[i4 * 4]) = v;
        reinterpret_cast<float4*>(g_sim)[b * (P / 4) + i4] = v;
    }
    __syncthreads();
    for (int r = 0; r < TOPK; r++) {
        float best = -3.4e38f; int idx = 0;
        for (int j = tid; j < P; j += 256) {   // ascending j: strict '>' keeps lowest idx
            float v = sv[j];
            if (v > best) { best = v; idx = j; }
        }
        bv[tid] = best; bi[tid] = idx;
        __syncthreads();
        for (int s = 128; s > 0; s >>= 1) {
            if (tid < s) {
                float v2 = bv[tid + s]; int i2 = bi[tid + s];
                if (v2 > bv[tid] || (v2 == bv[tid] && i2 < bi[tid])) {
                    bv[tid] = v2; bi[tid] = i2;
                }
            }
            __syncthreads();
        }
        if (tid == 0) {
            atomicAdd(&g_counts[bi[0]], 1);
            sv[bi[0]] = -3.4e38f;
        }
        __syncthreads();
    }
}

// ---------------- K6: vote top-8 of counts + reduce_sim ----------------------
__global__ __launch_bounds__(256) void k6_vote(float* __restrict__ out) {
    __shared__ int   cv[P];
    __shared__ int   bvv[256];
    __shared__ int   bii[256];
    __shared__ int   ms[TOPK];
    __shared__ float wsum[8];
    int tid = threadIdx.x;           // 0..255
    for (int i = tid; i < P; i += 256) cv[i] = g_counts[i];
    __syncthreads();
    for (int r = 0; r < TOPK; r++) {
        int best = -1, idx = 0;
        for (int j = tid; j < P; j += 256) {
            int v = cv[j];
            if (v > best) { best = v; idx = j; }
        }
        bvv[tid] = best; bii[tid] = idx;
        __syncthreads();
        for (int s = 128; s > 0; s >>= 1) {
            if (tid < s) {
                if (bvv[tid + s] > bvv[tid] ||
                    (bvv[tid + s] == bvv[tid] && bii[tid + s] < bii[tid])) {
                    bvv[tid] = bvv[tid + s]; bii[tid] = bii[tid + s];
                }
            }
            __syncthreads();
        }
        if (tid == 0) { ms[r] = bii[0]; g_mid[r] = bii[0]; cv[bii[0]] = -1; }
        __syncthreads();
    }
    // reduce_sim = sum_{b,j} sim[b, mid[j]] / B
    float s = 0.f;
    for (int t = tid; t < B * TOPK; t += 256) {
        int b = t >> 3, j = t & 7;
        s += g_sim[b * P + ms[j]];
    }
#pragma unroll
    for (int o = 16; o; o >>= 1) s += __shfl_xor_sync(0xffffffffu, s, o);
    if ((tid & 31) == 0) wsum[tid >> 5] = s;
    __syncthreads();
    if (tid == 0) {
        float tot = 0.f;
#pragma unroll
        for (int w = 0; w < 8; w++) tot += wsum[w];
        out[0] = tot / (float)B;
    }
}

// ---------------- K7: gather batched_prompt ----------------------------------
__global__ __launch_bounds__(192) void k7_gather(const float* __restrict__ prompt,
                                                 float* __restrict__ out) {
    int blk = blockIdx.x;            // b*8 + j, 512 blocks
    int j   = blk & 7;
    int pid = g_mid[j];
    int tid = threadIdx.x;           // 0..191
    const float* src = prompt + (size_t)pid * D;
    float* dst = out + 1 + (size_t)blk * D;   // out[0] = reduce_sim
#pragma unroll
    for (int k = 0; k < 4; k++) dst[tid + k * 192] = src[tid + k * 192];
}

// ---------------- launch ------------------------------------------------------
extern "C" void kernel_launch(void* const* d_in, const int* in_sizes, int n_in,
                              void* d_out, int out_size) {
    const float* x      = (const float*)d_in[0];
    const float* prompt = (const float*)d_in[1];
    const float* W      = (const float*)d_in[2];
    float* out          = (float*)d_out;

    k1_maxpart<<<B * NCH, 192>>>(x);
    k2f<<<B + P, 192>>>(prompt);          // fused maxfin + pnorm
    k3p<<<(D / 32) * KSPL, 256>>>(W);
    k3c_xnorm<<<B, 192>>>();
    k4p<<<(P / 32) * KSPL, 256>>>();
    k5_top8<<<B, 256>>>();
    k6_vote<<<1, 256>>>(out);
    k7_gather<<<B * TOPK, 192>>>(prompt, out);
}